// round 1
// baseline (speedup 1.0000x reference)
#include <cuda_runtime.h>
#include <cstdint>
#include <cstddef>

#define NP 200000
#define NA 100000
#define EC 4000000
#define EW 2000000

// ---------------- device scratch (allocation-free: __device__ globals) ----------------
__device__ float4 g_xlp[(size_t)NP * 16];   // x_paper @ gcn_W
__device__ float4 g_P  [(size_t)NP * 16];   // paper accumulation (gcn + sage)
__device__ float4 g_SA [(size_t)NP * 16];   // sage neighbor sum / mean
__device__ float4 g_XS [(size_t)NP * 16];   // gat source features (paper)
__device__ float4 g_XD [(size_t)NA * 16];   // gat dst features (author)
__device__ float4 g_xp1[(size_t)NP * 16];   // x_paper after layer 0
__device__ float4 g_xa1[(size_t)NA * 16];   // x_author after layer 0 / layer 1
__device__ float4 g_AO [(size_t)NA * 16];   // gat output accumulation
__device__ float  g_dis [NP];
__device__ float  g_rcnt[NP];
__device__ float  g_asrc[NP];
__device__ float  g_adst[NA];
__device__ float  g_den [NA];
__device__ float  g_e   [EW];
__device__ int    g_degi[NP];
__device__ int    g_cnti[NP];
__device__ unsigned g_mm[NA];

// ---------------- helpers ----------------
__device__ __forceinline__ void red4(float* addr, float4 v) {
    asm volatile("red.global.add.v4.f32 [%0], {%1,%2,%3,%4};"
                 :: "l"(addr), "f"(v.x), "f"(v.y), "f"(v.z), "f"(v.w) : "memory");
}

// order-preserving float<->uint map for atomicMax on floats
__device__ __forceinline__ unsigned fenc(float f) {
    unsigned u = __float_as_uint(f);
    return (u & 0x80000000u) ? ~u : (u | 0x80000000u);
}
__device__ __forceinline__ float fdec(unsigned u) {
    return (u & 0x80000000u) ? __uint_as_float(u & 0x7FFFFFFFu) : __uint_as_float(~u);
}
#define ENC_NEG_INF 0x007FFFFFu   // fenc(-inf)

// ---------------- small utility kernels ----------------
__global__ void k_zero_i(int* p, int n) {
    int i = blockIdx.x * blockDim.x + threadIdx.x;
    if (i < n) p[i] = 0;
}
__global__ void k_zero_f4(float4* p, int n) {
    int i = blockIdx.x * blockDim.x + threadIdx.x;
    if (i < n) p[i] = make_float4(0.f, 0.f, 0.f, 0.f);
}
__global__ void k_fill_u(unsigned* p, unsigned v, int n) {
    int i = blockIdx.x * blockDim.x + threadIdx.x;
    if (i < n) p[i] = v;
}
__global__ void k_zero_f(float* p, int n) {
    int i = blockIdx.x * blockDim.x + threadIdx.x;
    if (i < n) p[i] = 0.f;
}
__global__ void k_count(const int* __restrict__ idx, int* cnt, int E) {
    int i = blockIdx.x * blockDim.x + threadIdx.x;
    if (i < E) atomicAdd(&cnt[idx[i]], 1);
}
__global__ void k_dis(const int* __restrict__ cnt, float* dis, int n) {
    int i = blockIdx.x * blockDim.x + threadIdx.x;
    if (i < n) dis[i] = rsqrtf((float)cnt[i] + 1.0f);
}
__global__ void k_rcnt(const int* __restrict__ cnt, float* r, int n) {
    int i = blockIdx.x * blockDim.x + threadIdx.x;
    if (i < n) r[i] = 1.0f / fmaxf((float)cnt[i], 1.0f);
}

// P = xlp * dis^2 (GCN self-loop term)
__global__ void k_selfinit(const float4* __restrict__ xlp, const float* __restrict__ dis,
                           float4* __restrict__ P, int rows) {
    int i = blockIdx.x * blockDim.x + threadIdx.x;
    if (i >= rows * 16) return;
    float d = dis[i >> 4];
    float c = d * d;
    float4 v = xlp[i];
    v.x *= c; v.y *= c; v.z *= c; v.w *= c;
    P[i] = v;
}

// out[dst] += xl[src] * dis[src]*dis[dst]    (16 threads per edge, float4 each)
__global__ void k_gcn_scatter(const int* __restrict__ src, const int* __restrict__ dst,
                              const float* __restrict__ dis, const float4* __restrict__ xl,
                              float* __restrict__ out, int E) {
    int gid = blockIdx.x * blockDim.x + threadIdx.x;
    int e = gid >> 4;
    if (e >= E) return;
    int j = gid & 15;
    int s = src[e], d = dst[e];
    float c = dis[s] * dis[d];
    float4 v = xl[(size_t)s * 16 + j];
    v.x *= c; v.y *= c; v.z *= c; v.w *= c;
    red4(&out[(size_t)d * 64 + j * 4], v);
}

// out[dst] += xsrc[src]    (sage neighbor sum)
__global__ void k_sage_scatter(const int* __restrict__ src, const int* __restrict__ dst,
                               const float4* __restrict__ xsrc, float* __restrict__ out, int E) {
    int gid = blockIdx.x * blockDim.x + threadIdx.x;
    int e = gid >> 4;
    if (e >= E) return;
    int j = gid & 15;
    int s = src[e], d = dst[e];
    float4 v = xsrc[(size_t)s * 16 + j];
    red4(&out[(size_t)d * 64 + j * 4], v);
}

// p[row] *= s[row] (per-row scale, vectorized)
__global__ void k_scale_rows(float4* p, const float* __restrict__ s, int rows) {
    int i = blockIdx.x * blockDim.x + threadIdx.x;
    if (i >= rows * 16) return;
    float c = s[i >> 4];
    float4 v = p[i];
    v.x *= c; v.y *= c; v.z *= c; v.w *= c;
    p[i] = v;
}

// out[r] = dot(X[r,:64], v)  -- one warp per row
__global__ void k_rowdot(const float* __restrict__ X, const float* __restrict__ v,
                         float* __restrict__ out, int M) {
    int t = blockIdx.x * blockDim.x + threadIdx.x;
    int w = t >> 5, lane = t & 31;
    if (w >= M) return;
    const float* xr = X + (size_t)w * 64;
    float a = xr[lane] * v[lane] + xr[lane + 32] * v[lane + 32];
    #pragma unroll
    for (int o = 16; o > 0; o >>= 1) a += __shfl_xor_sync(0xFFFFFFFFu, a, o);
    if (lane == 0) out[w] = a;
}

// GAT pass 1: e = leaky(a_src[paper] + a_dst[author]); segment max into mm[author]
__global__ void k_gat1(const int* __restrict__ pidx, const int* __restrict__ aidx,
                       const float* __restrict__ asrc, const float* __restrict__ adst,
                       float* __restrict__ eo, unsigned* __restrict__ mm, int E) {
    int i = blockIdx.x * blockDim.x + threadIdx.x;
    if (i >= E) return;
    int p = pidx[i], a = aidx[i];
    float x = asrc[p] + adst[a];
    x = (x > 0.f) ? x : 0.2f * x;
    eo[i] = x;
    atomicMax(&mm[a], fenc(x));
}

// GAT pass 2: ex = exp(e - m[a]); denom[a] += ex; e <- ex
__global__ void k_gat2(const int* __restrict__ aidx, const unsigned* __restrict__ mm,
                       float* __restrict__ e, float* __restrict__ den, int E) {
    int i = blockIdx.x * blockDim.x + threadIdx.x;
    if (i >= E) return;
    int a = aidx[i];
    float m = fdec(mm[a]);
    float ex = __expf(e[i] - m);
    e[i] = ex;
    atomicAdd(&den[a], ex);
}

// GAT pass 3: AO[a] += (ex/denom[a]) * XS[p]
__global__ void k_gat3(const int* __restrict__ pidx, const int* __restrict__ aidx,
                       const float* __restrict__ ex, const float* __restrict__ den,
                       const float4* __restrict__ XS, float* __restrict__ AO, int E) {
    int gid = blockIdx.x * blockDim.x + threadIdx.x;
    int e = gid >> 4;
    if (e >= E) return;
    int j = gid & 15;
    int p = pidx[e], a = aidx[e];
    float al = ex[e] / den[a];
    float4 v = XS[(size_t)p * 16 + j];
    v.x *= al; v.y *= al; v.z *= al; v.w *= al;
    red4(&AO[(size_t)a * 64 + j * 4], v);
}

// out = relu(A + b0[col] (+ b1[col]))  (H=64 per row)
__global__ void k_combine(const float4* __restrict__ A, const float* __restrict__ b0,
                          const float* __restrict__ b1, float4* __restrict__ out, int rows) {
    int i = blockIdx.x * blockDim.x + threadIdx.x;
    if (i >= rows * 16) return;
    int c = i & 15;
    float4 v = A[i];
    float4 b = ((const float4*)b0)[c];
    v.x += b.x; v.y += b.y; v.z += b.z; v.w += b.w;
    if (b1) {
        float4 b2 = ((const float4*)b1)[c];
        v.x += b2.x; v.y += b2.y; v.z += b2.z; v.w += b2.w;
    }
    v.x = fmaxf(v.x, 0.f); v.y = fmaxf(v.y, 0.f);
    v.z = fmaxf(v.z, 0.f); v.w = fmaxf(v.w, 0.f);
    out[i] = v;
}

// ---------------- tall-skinny GEMM: Y[M,N] (+)= X[M,K] @ W[K,N] (+ bias) ----------------
template <int K, int N>
__global__ void k_gemm(const float* __restrict__ X, const float* __restrict__ W,
                       const float* __restrict__ bias, float* __restrict__ Y,
                       int M, int acc) {
    __shared__ __align__(16) float Wc[32 * N];
    __shared__ __align__(16) float Xs[128 * 33];
    int tid = threadIdx.x;
    int base = blockIdx.x * 128;
    int row = base + tid;

    float accv[N];
    #pragma unroll
    for (int n = 0; n < N; n++) accv[n] = 0.f;

    for (int kc = 0; kc < K; kc += 32) {
        __syncthreads();
        // stage W rows [kc, kc+32)
        #pragma unroll
        for (int i = 0; i < (32 * N) / 128; i++) {
            int t = tid + i * 128;
            Wc[t] = W[kc * N + t];
        }
        // stage X tile [base..base+128) x [kc..kc+32), coalesced
        #pragma unroll
        for (int i = 0; i < 32; i++) {
            int t = tid + i * 128;
            int r = t >> 5, c = t & 31;
            int rr = base + r;
            Xs[r * 33 + c] = (rr < M) ? X[(size_t)rr * K + kc + c] : 0.f;
        }
        __syncthreads();
        if (row < M) {
            #pragma unroll
            for (int k = 0; k < 32; k++) {
                float xv = Xs[tid * 33 + k];
                #pragma unroll
                for (int n = 0; n < N; n += 4) {
                    float4 w = *(const float4*)&Wc[k * N + n];
                    accv[n]     += xv * w.x;
                    accv[n + 1] += xv * w.y;
                    accv[n + 2] += xv * w.z;
                    accv[n + 3] += xv * w.w;
                }
            }
        }
    }
    if (row < M) {
        #pragma unroll
        for (int n = 0; n < N; n += 4) {
            float4 o = make_float4(accv[n], accv[n + 1], accv[n + 2], accv[n + 3]);
            if (bias) {
                o.x += bias[n]; o.y += bias[n + 1]; o.z += bias[n + 2]; o.w += bias[n + 3];
            }
            float4* yp = (float4*)&Y[(size_t)row * N + n];
            if (acc) {
                float4 old = *yp;
                o.x += old.x; o.y += old.y; o.z += old.z; o.w += old.w;
            }
            *yp = o;
        }
    }
}

// ---------------- host ----------------
static inline int cdiv(long long a, int b) { return (int)((a + b - 1) / b); }

extern "C" void kernel_launch(void* const* d_in, const int* in_sizes, int n_in,
                              void* d_out, int out_size) {
    const float* xp      = (const float*)d_in[0];
    const float* xa      = (const float*)d_in[1];
    const float* gcn_W0  = (const float*)d_in[2];
    const float* gcn_b0  = (const float*)d_in[3];
    const float* sage_Wl0= (const float*)d_in[4];
    const float* sage_bl0= (const float*)d_in[5];
    const float* sage_Wr0= (const float*)d_in[6];
    const float* gat_Ws0 = (const float*)d_in[7];
    const float* gat_Wd0 = (const float*)d_in[8];
    const float* gat_as0 = (const float*)d_in[9];
    const float* gat_ad0 = (const float*)d_in[10];
    const float* gat_b0  = (const float*)d_in[11];
    // layer1: only GAT params are live (paper update of layer1 is dead code)
    const float* gat_Ws1 = (const float*)d_in[17];
    const float* gat_Wd1 = (const float*)d_in[18];
    const float* gat_as1 = (const float*)d_in[19];
    const float* gat_ad1 = (const float*)d_in[20];
    const float* gat_b1  = (const float*)d_in[21];
    const float* lin_W   = (const float*)d_in[22];
    const float* lin_b   = (const float*)d_in[23];
    const int* cs = (const int*)d_in[24];
    const int* cd = (const int*)d_in[25];
    const int* ws = (const int*)d_in[26];  // author index of writes edge
    const int* wd = (const int*)d_in[27];  // paper index of writes edge
    float* out = (float*)d_out;

    // fetch scratch addresses
    void *p_xlp, *p_P, *p_SA, *p_XS, *p_XD, *p_xp1, *p_xa1, *p_AO;
    void *p_dis, *p_rcnt, *p_asrc, *p_adst, *p_den, *p_e, *p_degi, *p_cnti, *p_mm;
    cudaGetSymbolAddress(&p_xlp, g_xlp);   cudaGetSymbolAddress(&p_P, g_P);
    cudaGetSymbolAddress(&p_SA, g_SA);     cudaGetSymbolAddress(&p_XS, g_XS);
    cudaGetSymbolAddress(&p_XD, g_XD);     cudaGetSymbolAddress(&p_xp1, g_xp1);
    cudaGetSymbolAddress(&p_xa1, g_xa1);   cudaGetSymbolAddress(&p_AO, g_AO);
    cudaGetSymbolAddress(&p_dis, g_dis);   cudaGetSymbolAddress(&p_rcnt, g_rcnt);
    cudaGetSymbolAddress(&p_asrc, g_asrc); cudaGetSymbolAddress(&p_adst, g_adst);
    cudaGetSymbolAddress(&p_den, g_den);   cudaGetSymbolAddress(&p_e, g_e);
    cudaGetSymbolAddress(&p_degi, g_degi); cudaGetSymbolAddress(&p_cnti, g_cnti);
    cudaGetSymbolAddress(&p_mm, g_mm);

    float4* xlp = (float4*)p_xlp;  float4* P   = (float4*)p_P;
    float4* SA  = (float4*)p_SA;   float4* XS  = (float4*)p_XS;
    float4* XD  = (float4*)p_XD;   float4* xp1 = (float4*)p_xp1;
    float4* xa1 = (float4*)p_xa1;  float4* AO  = (float4*)p_AO;
    float* dis  = (float*)p_dis;   float* rcnt = (float*)p_rcnt;
    float* asrc = (float*)p_asrc;  float* adst = (float*)p_adst;
    float* den  = (float*)p_den;   float* ev   = (float*)p_e;
    int* degi   = (int*)p_degi;    int* cnti   = (int*)p_cnti;
    unsigned* mm = (unsigned*)p_mm;

    const int T = 256;

    // degrees / counts (shared across layer 0)
    k_zero_i<<<cdiv(NP, T), T>>>(degi, NP);
    k_zero_i<<<cdiv(NP, T), T>>>(cnti, NP);
    k_count<<<cdiv(EC, T), T>>>(cd, degi, EC);
    k_count<<<cdiv(EW, T), T>>>(wd, cnti, EW);
    k_dis<<<cdiv(NP, T), T>>>(degi, dis, NP);
    k_rcnt<<<cdiv(NP, T), T>>>(cnti, rcnt, NP);

    // ---- layer 0: GCN (paper<-paper) ----
    k_gemm<128, 64><<<cdiv(NP, 128), 128>>>(xp, gcn_W0, nullptr, (float*)xlp, NP, 0);
    k_selfinit<<<cdiv((long long)NP * 16, T), T>>>(xlp, dis, P, NP);
    k_gcn_scatter<<<cdiv((long long)EC * 16, T), T>>>(cs, cd, dis, xlp, (float*)P, EC);

    // ---- layer 0: SAGE (paper<-author) ----
    k_zero_f4<<<cdiv((long long)NP * 16, T), T>>>(SA, NP * 16);
    k_sage_scatter<<<cdiv((long long)EW * 16, T), T>>>(ws, wd, (const float4*)xa, (float*)SA, EW);
    k_scale_rows<<<cdiv((long long)NP * 16, T), T>>>(SA, rcnt, NP);
    k_gemm<128, 64><<<cdiv(NP, 128), 128>>>(xp, sage_Wr0, nullptr, (float*)P, NP, 1);
    k_gemm<64, 64><<<cdiv(NP, 128), 128>>>((const float*)SA, sage_Wl0, nullptr, (float*)P, NP, 1);

    // ---- layer 0: GAT (author<-paper) ----
    k_gemm<128, 64><<<cdiv(NP, 128), 128>>>(xp, gat_Ws0, nullptr, (float*)XS, NP, 0);
    k_gemm<64, 64><<<cdiv(NA, 128), 128>>>(xa, gat_Wd0, nullptr, (float*)XD, NA, 0);
    k_rowdot<<<cdiv((long long)NP * 32, T), T>>>((const float*)XS, gat_as0, asrc, NP);
    k_rowdot<<<cdiv((long long)NA * 32, T), T>>>((const float*)XD, gat_ad0, adst, NA);
    k_fill_u<<<cdiv(NA, T), T>>>(mm, ENC_NEG_INF, NA);
    k_zero_f<<<cdiv(NA, T), T>>>(den, NA);
    k_gat1<<<cdiv(EW, T), T>>>(wd, ws, asrc, adst, ev, mm, EW);
    k_gat2<<<cdiv(EW, T), T>>>(ws, mm, ev, den, EW);
    k_zero_f4<<<cdiv((long long)NA * 16, T), T>>>(AO, NA * 16);
    k_gat3<<<cdiv((long long)EW * 16, T), T>>>(wd, ws, ev, den, XS, (float*)AO, EW);

    // ---- layer 0 combine ----
    k_combine<<<cdiv((long long)NP * 16, T), T>>>(P, gcn_b0, sage_bl0, xp1, NP);
    k_combine<<<cdiv((long long)NA * 16, T), T>>>(AO, gat_b0, nullptr, xa1, NA);

    // ---- layer 1: only GAT is live ----
    k_gemm<64, 64><<<cdiv(NP, 128), 128>>>((const float*)xp1, gat_Ws1, nullptr, (float*)XS, NP, 0);
    k_gemm<64, 64><<<cdiv(NA, 128), 128>>>((const float*)xa1, gat_Wd1, nullptr, (float*)XD, NA, 0);
    k_rowdot<<<cdiv((long long)NP * 32, T), T>>>((const float*)XS, gat_as1, asrc, NP);
    k_rowdot<<<cdiv((long long)NA * 32, T), T>>>((const float*)XD, gat_ad1, adst, NA);
    k_fill_u<<<cdiv(NA, T), T>>>(mm, ENC_NEG_INF, NA);
    k_zero_f<<<cdiv(NA, T), T>>>(den, NA);
    k_gat1<<<cdiv(EW, T), T>>>(wd, ws, asrc, adst, ev, mm, EW);
    k_gat2<<<cdiv(EW, T), T>>>(ws, mm, ev, den, EW);
    k_zero_f4<<<cdiv((long long)NA * 16, T), T>>>(AO, NA * 16);
    k_gat3<<<cdiv((long long)EW * 16, T), T>>>(wd, ws, ev, den, XS, (float*)AO, EW);
    k_combine<<<cdiv((long long)NA * 16, T), T>>>(AO, gat_b1, nullptr, xa1, NA);

    // ---- output head ----
    k_gemm<64, 32><<<cdiv(NA, 128), 128>>>((const float*)xa1, lin_W, lin_b, out, NA, 0);
}

// round 3
// speedup vs baseline: 1.4046x; 1.4046x over previous
#include <cuda_runtime.h>
#include <cstdint>
#include <cstddef>

#define NP 200000
#define NA 100000
#define EC 4000000
#define EW 2000000

// ---------------- device scratch (allocation-free) ----------------
__device__ float g_xls[(size_t)NP * 64];   // dis-scaled x_paper @ gcn_W
__device__ float g_P  [(size_t)NP * 64];   // paper accumulation
__device__ float g_SA [(size_t)NP * 64];   // sage neighbor mean
__device__ float g_XS [(size_t)NP * 64];   // gat source feats (paper)
__device__ float g_XD [(size_t)NA * 64];   // gat dst feats (author)
__device__ float g_xp1[(size_t)NP * 64];   // x_paper after layer 0
__device__ float g_xa1[(size_t)NA * 64];   // x_author after layer 0/1
__device__ float g_dis [NP];
__device__ float g_asrc[NP];
__device__ float g_adst[NA];
__device__ int g_degC[NP], g_degWp[NP], g_degWa[NA];
__device__ int g_offC[NP], g_offWp[NP], g_offWa[NA];
__device__ int g_curC[NP], g_curWp[NP], g_curWa[NA];
__device__ int g_bsum[512];
__device__ int g_csrC[EC], g_csrWp[EW], g_csrWa[EW];

// ---------------- utility kernels ----------------
__global__ void k_zero_i(int* p, int n) {
    int i = blockIdx.x * blockDim.x + threadIdx.x;
    if (i < n) p[i] = 0;
}
__global__ void k_count(const int* __restrict__ idx, int* cnt, int E) {
    int i = blockIdx.x * blockDim.x + threadIdx.x;
    if (i < E) atomicAdd(&cnt[idx[i]], 1);
}
__global__ void k_dis(const int* __restrict__ cnt, float* dis, int n) {
    int i = blockIdx.x * blockDim.x + threadIdx.x;
    if (i < n) dis[i] = rsqrtf((float)cnt[i] + 1.0f);
}

// ---------------- scan (3-phase, blocks of 512) ----------------
__global__ void k_scan1(const int* __restrict__ deg, int* off, int* bsum, int n) {
    __shared__ int sh[512];
    int t = threadIdx.x, i = blockIdx.x * 512 + t;
    int v = (i < n) ? deg[i] : 0;
    sh[t] = v; __syncthreads();
    #pragma unroll
    for (int o = 1; o < 512; o <<= 1) {
        int x = (t >= o) ? sh[t - o] : 0;
        __syncthreads(); sh[t] += x; __syncthreads();
    }
    if (i < n) off[i] = sh[t] - v;
    if (t == 511) bsum[blockIdx.x] = sh[511];
}
__global__ void k_scan2(int* bsum, int nb) {
    __shared__ int sh[512];
    int t = threadIdx.x;
    int v = (t < nb) ? bsum[t] : 0;
    sh[t] = v; __syncthreads();
    #pragma unroll
    for (int o = 1; o < 512; o <<= 1) {
        int x = (t >= o) ? sh[t - o] : 0;
        __syncthreads(); sh[t] += x; __syncthreads();
    }
    if (t < nb) bsum[t] = sh[t] - v;
}
__global__ void k_scan3(int* off, int* cur, const int* __restrict__ bsum, int n) {
    int i = blockIdx.x * blockDim.x + threadIdx.x;
    if (i < n) { int v = off[i] + bsum[i >> 9]; off[i] = v; cur[i] = v; }
}
__global__ void k_fill(const int* __restrict__ dst, const int* __restrict__ src,
                       int* cur, int* csr, int E) {
    int i = blockIdx.x * blockDim.x + threadIdx.x;
    if (i < E) {
        int pos = atomicAdd(&cur[dst[i]], 1);
        csr[pos] = src[i];
    }
}

// ---------------- gathers (1 warp / node, 2 cols / lane) ----------------
__global__ void k_gcn_gather(const int* __restrict__ off, const int* __restrict__ csr,
                             const float* __restrict__ xls, const float* __restrict__ dis,
                             float* __restrict__ P, int n, int E) {
    int w = (blockIdx.x * blockDim.x + threadIdx.x) >> 5;
    int lane = threadIdx.x & 31;
    if (w >= n) return;
    int beg = off[w], end = (w == n - 1) ? E : off[w + 1];
    float a0 = 0.f, a1 = 0.f;
    int t = beg;
    for (; t + 4 <= end; t += 4) {
        int s0 = __ldg(&csr[t]),     s1 = __ldg(&csr[t + 1]);
        int s2 = __ldg(&csr[t + 2]), s3 = __ldg(&csr[t + 3]);
        float b0 = xls[s0 * 64 + lane],      c0 = xls[s0 * 64 + 32 + lane];
        float b1 = xls[s1 * 64 + lane],      c1 = xls[s1 * 64 + 32 + lane];
        float b2 = xls[s2 * 64 + lane],      c2 = xls[s2 * 64 + 32 + lane];
        float b3 = xls[s3 * 64 + lane],      c3 = xls[s3 * 64 + 32 + lane];
        a0 += (b0 + b1) + (b2 + b3);
        a1 += (c0 + c1) + (c2 + c3);
    }
    for (; t < end; t++) {
        int s = __ldg(&csr[t]);
        a0 += xls[s * 64 + lane];
        a1 += xls[s * 64 + 32 + lane];
    }
    float dd = dis[w];
    P[(size_t)w * 64 + lane]      = dd * (a0 + xls[w * 64 + lane]);
    P[(size_t)w * 64 + 32 + lane] = dd * (a1 + xls[w * 64 + 32 + lane]);
}

__global__ void k_sage_gather(const int* __restrict__ off, const int* __restrict__ csr,
                              const float* __restrict__ xa, float* __restrict__ SA,
                              int n, int E) {
    int w = (blockIdx.x * blockDim.x + threadIdx.x) >> 5;
    int lane = threadIdx.x & 31;
    if (w >= n) return;
    int beg = off[w], end = (w == n - 1) ? E : off[w + 1];
    float a0 = 0.f, a1 = 0.f;
    int t = beg;
    for (; t + 4 <= end; t += 4) {
        int s0 = __ldg(&csr[t]),     s1 = __ldg(&csr[t + 1]);
        int s2 = __ldg(&csr[t + 2]), s3 = __ldg(&csr[t + 3]);
        float b0 = xa[s0 * 64 + lane],      c0 = xa[s0 * 64 + 32 + lane];
        float b1 = xa[s1 * 64 + lane],      c1 = xa[s1 * 64 + 32 + lane];
        float b2 = xa[s2 * 64 + lane],      c2 = xa[s2 * 64 + 32 + lane];
        float b3 = xa[s3 * 64 + lane],      c3 = xa[s3 * 64 + 32 + lane];
        a0 += (b0 + b1) + (b2 + b3);
        a1 += (c0 + c1) + (c2 + c3);
    }
    for (; t < end; t++) {
        int s = __ldg(&csr[t]);
        a0 += xa[s * 64 + lane];
        a1 += xa[s * 64 + 32 + lane];
    }
    float r = 1.0f / fmaxf((float)(end - beg), 1.0f);
    SA[(size_t)w * 64 + lane]      = a0 * r;
    SA[(size_t)w * 64 + 32 + lane] = a1 * r;
}

// fused GAT: per-author softmax(denominator) + weighted gather + bias + relu
__global__ void k_gat_gather(const int* __restrict__ off, const int* __restrict__ csr,
                             const float* __restrict__ asrc, const float* __restrict__ adst,
                             const float* __restrict__ XS, const float* __restrict__ bias,
                             float* __restrict__ out, int n, int E) {
    int w = (blockIdx.x * blockDim.x + threadIdx.x) >> 5;
    int lane = threadIdx.x & 31;
    if (w >= n) return;
    int beg = off[w], end = (w == n - 1) ? E : off[w + 1];
    float ad = adst[w];
    float den = 0.f, a0 = 0.f, a1 = 0.f;
    int t = beg;
    for (; t + 2 <= end; t += 2) {
        int p0 = __ldg(&csr[t]), p1 = __ldg(&csr[t + 1]);
        float e0 = asrc[p0] + ad; e0 = (e0 > 0.f) ? e0 : 0.2f * e0;
        float e1 = asrc[p1] + ad; e1 = (e1 > 0.f) ? e1 : 0.2f * e1;
        float x0 = __expf(e0), x1 = __expf(e1);
        float b0 = XS[p0 * 64 + lane],      c0 = XS[p0 * 64 + 32 + lane];
        float b1 = XS[p1 * 64 + lane],      c1 = XS[p1 * 64 + 32 + lane];
        den += x0 + x1;
        a0 += x0 * b0 + x1 * b1;
        a1 += x0 * c0 + x1 * c1;
    }
    for (; t < end; t++) {
        int p = __ldg(&csr[t]);
        float e = asrc[p] + ad; e = (e > 0.f) ? e : 0.2f * e;
        float x = __expf(e);
        den += x;
        a0 += x * XS[p * 64 + lane];
        a1 += x * XS[p * 64 + 32 + lane];
    }
    float r = (den > 0.f) ? (1.0f / den) : 0.f;
    float o0 = a0 * r + bias[lane];
    float o1 = a1 * r + bias[lane + 32];
    out[(size_t)w * 64 + lane]      = fmaxf(o0, 0.f);
    out[(size_t)w * 64 + 32 + lane] = fmaxf(o1, 0.f);
}

// out[r] = dot(X[r,:64], v) -- one warp per row
__global__ void k_rowdot(const float* __restrict__ X, const float* __restrict__ v,
                         float* __restrict__ out, int M) {
    int t = blockIdx.x * blockDim.x + threadIdx.x;
    int w = t >> 5, lane = t & 31;
    if (w >= M) return;
    const float* xr = X + (size_t)w * 64;
    float a = xr[lane] * v[lane] + xr[lane + 32] * v[lane + 32];
    #pragma unroll
    for (int o = 16; o > 0; o >>= 1) a += __shfl_xor_sync(0xFFFFFFFFu, a, o);
    if (lane == 0) out[w] = a;
}

// xp1 = relu(P + b0 + b1)
__global__ void k_combine(const float4* __restrict__ A, const float* __restrict__ b0,
                          const float* __restrict__ b1, float4* __restrict__ out, int rows) {
    int i = blockIdx.x * blockDim.x + threadIdx.x;
    if (i >= rows * 16) return;
    int c = i & 15;
    float4 v = A[i];
    float4 b = ((const float4*)b0)[c];
    float4 b2 = ((const float4*)b1)[c];
    v.x = fmaxf(v.x + b.x + b2.x, 0.f);
    v.y = fmaxf(v.y + b.y + b2.y, 0.f);
    v.z = fmaxf(v.z + b.z + b2.z, 0.f);
    v.w = fmaxf(v.w + b.w + b2.w, 0.f);
    out[i] = v;
}

// ---------------- f32x2 register-blocked GEMM ----------------
// Y[M,N] (+)= X[M,K] @ W[K,N] (+bias) (*rowscale). 256 thr, tile M=128.
// thread = 4 rows x CPT cols (CPT = N/8). Packed fma.rn.f32x2, A duplicated in smem.
template <int K, int N>
__global__ void __launch_bounds__(256) k_gemm2(
        const float* __restrict__ X, const float* __restrict__ W,
        const float* __restrict__ bias, const float* __restrict__ rowscale,
        float* __restrict__ Y, int M, int acc) {
    constexpr int CPT = N / 8;      // 8 (N=64) or 4 (N=32)
    constexpr int QP  = CPT / 2;    // f32x2 pairs per thread
    __shared__ __align__(16) float  Wc[32 * N];
    __shared__ __align__(16) float2 Xd[128 * 33];
    int tid = threadIdx.x;
    int tx = tid & 7, ty = tid >> 3;
    int base = blockIdx.x * 128;

    unsigned long long accv[4][QP];
    #pragma unroll
    for (int i = 0; i < 4; i++)
        #pragma unroll
        for (int q = 0; q < QP; q++) accv[i][q] = 0ull;

    for (int kc = 0; kc < K; kc += 32) {
        __syncthreads();
        #pragma unroll
        for (int it = 0; it < (32 * N) / 256; it++) {
            int t = tid + it * 256;
            Wc[t] = W[kc * N + t];
        }
        #pragma unroll
        for (int it = 0; it < 16; it++) {
            int idx = tid + it * 256;
            int r = idx >> 5, k = idx & 31;
            int rr = base + r;
            float v = (rr < M) ? X[(size_t)rr * K + kc + k] : 0.f;
            Xd[r * 33 + k] = make_float2(v, v);
        }
        __syncthreads();
        #pragma unroll
        for (int k = 0; k < 32; k++) {
            unsigned long long a[4];
            #pragma unroll
            for (int i = 0; i < 4; i++)
                a[i] = *(const unsigned long long*)&Xd[(ty * 4 + i) * 33 + k];
            #pragma unroll
            for (int h = 0; h < QP / 2; h++) {
                ulonglong2 wp = *(const ulonglong2*)&Wc[k * N + tx * CPT + h * 4];
                #pragma unroll
                for (int i = 0; i < 4; i++) {
                    asm("fma.rn.f32x2 %0, %1, %2, %0;"
                        : "+l"(accv[i][2 * h]) : "l"(a[i]), "l"(wp.x));
                    asm("fma.rn.f32x2 %0, %1, %2, %0;"
                        : "+l"(accv[i][2 * h + 1]) : "l"(a[i]), "l"(wp.y));
                }
            }
        }
    }
    #pragma unroll
    for (int i = 0; i < 4; i++) {
        int row = base + ty * 4 + i;
        if (row >= M) continue;
        float rs = rowscale ? rowscale[row] : 1.f;
        #pragma unroll
        for (int q = 0; q < QP; q++) {
            float2 v = *(float2*)&accv[i][q];
            int col = tx * CPT + 2 * q;
            if (bias) { v.x += bias[col]; v.y += bias[col + 1]; }
            v.x *= rs; v.y *= rs;
            float2* yp = (float2*)&Y[(size_t)row * N + col];
            if (acc) { float2 o = *yp; v.x += o.x; v.y += o.y; }
            *yp = v;
        }
    }
}

// ---------------- host ----------------
static inline int cdiv(long long a, int b) { return (int)((a + b - 1) / b); }

extern "C" void kernel_launch(void* const* d_in, const int* in_sizes, int n_in,
                              void* d_out, int out_size) {
    const float* xp       = (const float*)d_in[0];
    const float* xa       = (const float*)d_in[1];
    const float* gcn_W0   = (const float*)d_in[2];
    const float* gcn_b0   = (const float*)d_in[3];
    const float* sage_Wl0 = (const float*)d_in[4];
    const float* sage_bl0 = (const float*)d_in[5];
    const float* sage_Wr0 = (const float*)d_in[6];
    const float* gat_Ws0  = (const float*)d_in[7];
    const float* gat_Wd0  = (const float*)d_in[8];
    const float* gat_as0  = (const float*)d_in[9];
    const float* gat_ad0  = (const float*)d_in[10];
    const float* gat_b0   = (const float*)d_in[11];
    const float* gat_Ws1  = (const float*)d_in[17];
    const float* gat_Wd1  = (const float*)d_in[18];
    const float* gat_as1  = (const float*)d_in[19];
    const float* gat_ad1  = (const float*)d_in[20];
    const float* gat_b1   = (const float*)d_in[21];
    const float* lin_W    = (const float*)d_in[22];
    const float* lin_b    = (const float*)d_in[23];
    const int* cs = (const int*)d_in[24];
    const int* cd = (const int*)d_in[25];
    const int* ws = (const int*)d_in[26];  // author idx of writes edge
    const int* wd = (const int*)d_in[27];  // paper idx of writes edge
    float* out = (float*)d_out;

    void *p;
    #define SYM(name) cudaGetSymbolAddress(&p, g_##name)
    SYM(xls);  float* xls = (float*)p;
    SYM(P);    float* P   = (float*)p;
    SYM(SA);   float* SA  = (float*)p;
    SYM(XS);   float* XS  = (float*)p;
    SYM(XD);   float* XD  = (float*)p;
    SYM(xp1);  float* xp1 = (float*)p;
    SYM(xa1);  float* xa1 = (float*)p;
    SYM(dis);  float* dis = (float*)p;
    SYM(asrc); float* asrc = (float*)p;
    SYM(adst); float* adst = (float*)p;
    SYM(degC); int* degC = (int*)p;
    SYM(degWp); int* degWp = (int*)p;
    SYM(degWa); int* degWa = (int*)p;
    SYM(offC); int* offC = (int*)p;
    SYM(offWp); int* offWp = (int*)p;
    SYM(offWa); int* offWa = (int*)p;
    SYM(curC); int* curC = (int*)p;
    SYM(curWp); int* curWp = (int*)p;
    SYM(curWa); int* curWa = (int*)p;
    SYM(bsum); int* bsum = (int*)p;
    SYM(csrC); int* csrC = (int*)p;
    SYM(csrWp); int* csrWp = (int*)p;
    SYM(csrWa); int* csrWa = (int*)p;
    #undef SYM

    const int T = 256;

    // ---- CSR build: cites-by-dst(paper), writes-by-paper, writes-by-author ----
    k_zero_i<<<cdiv(NP, T), T>>>(degC, NP);
    k_zero_i<<<cdiv(NP, T), T>>>(degWp, NP);
    k_zero_i<<<cdiv(NA, T), T>>>(degWa, NA);
    k_count<<<cdiv(EC, T), T>>>(cd, degC, EC);
    k_count<<<cdiv(EW, T), T>>>(wd, degWp, EW);
    k_count<<<cdiv(EW, T), T>>>(ws, degWa, EW);
    k_dis<<<cdiv(NP, T), T>>>(degC, dis, NP);

    k_scan1<<<cdiv(NP, 512), 512>>>(degC, offC, bsum, NP);
    k_scan2<<<1, 512>>>(bsum, cdiv(NP, 512));
    k_scan3<<<cdiv(NP, T), T>>>(offC, curC, bsum, NP);
    k_fill<<<cdiv(EC, T), T>>>(cd, cs, curC, csrC, EC);

    k_scan1<<<cdiv(NP, 512), 512>>>(degWp, offWp, bsum, NP);
    k_scan2<<<1, 512>>>(bsum, cdiv(NP, 512));
    k_scan3<<<cdiv(NP, T), T>>>(offWp, curWp, bsum, NP);
    k_fill<<<cdiv(EW, T), T>>>(wd, ws, curWp, csrWp, EW);

    k_scan1<<<cdiv(NA, 512), 512>>>(degWa, offWa, bsum, NA);
    k_scan2<<<1, 512>>>(bsum, cdiv(NA, 512));
    k_scan3<<<cdiv(NA, T), T>>>(offWa, curWa, bsum, NA);
    k_fill<<<cdiv(EW, T), T>>>(ws, wd, curWa, csrWa, EW);

    // ---- layer 0: GCN (paper<-paper) ----
    k_gemm2<128, 64><<<cdiv(NP, 128), 256>>>(xp, gcn_W0, nullptr, dis, xls, NP, 0);
    k_gcn_gather<<<cdiv((long long)NP * 32, T), T>>>(offC, csrC, xls, dis, P, NP, EC);

    // ---- layer 0: SAGE (paper<-author) ----
    k_sage_gather<<<cdiv((long long)NP * 32, T), T>>>(offWp, csrWp, xa, SA, NP, EW);
    k_gemm2<128, 64><<<cdiv(NP, 128), 256>>>(xp, sage_Wr0, nullptr, nullptr, P, NP, 1);
    k_gemm2<64, 64><<<cdiv(NP, 128), 256>>>(SA, sage_Wl0, nullptr, nullptr, P, NP, 1);
    k_combine<<<cdiv((long long)NP * 16, T), T>>>((const float4*)P, gcn_b0, sage_bl0,
                                                  (float4*)xp1, NP);

    // ---- layer 0: GAT (author<-paper) ----
    k_gemm2<128, 64><<<cdiv(NP, 128), 256>>>(xp, gat_Ws0, nullptr, nullptr, XS, NP, 0);
    k_gemm2<64, 64><<<cdiv(NA, 128), 256>>>(xa, gat_Wd0, nullptr, nullptr, XD, NA, 0);
    k_rowdot<<<cdiv((long long)NP * 32, T), T>>>(XS, gat_as0, asrc, NP);
    k_rowdot<<<cdiv((long long)NA * 32, T), T>>>(XD, gat_ad0, adst, NA);
    k_gat_gather<<<cdiv((long long)NA * 32, T), T>>>(offWa, csrWa, asrc, adst, XS,
                                                     gat_b0, xa1, NA, EW);

    // ---- layer 1: only GAT is live (paper update is dead code) ----
    k_gemm2<64, 64><<<cdiv(NP, 128), 256>>>(xp1, gat_Ws1, nullptr, nullptr, XS, NP, 0);
    k_gemm2<64, 64><<<cdiv(NA, 128), 256>>>(xa1, gat_Wd1, nullptr, nullptr, XD, NA, 0);
    k_rowdot<<<cdiv((long long)NP * 32, T), T>>>(XS, gat_as1, asrc, NP);
    k_rowdot<<<cdiv((long long)NA * 32, T), T>>>(XD, gat_ad1, adst, NA);
    k_gat_gather<<<cdiv((long long)NA * 32, T), T>>>(offWa, csrWa, asrc, adst, XS,
                                                     gat_b1, xa1, NA, EW);

    // ---- output head ----
    k_gemm2<64, 32><<<cdiv(NA, 128), 256>>>(xa1, lin_W, lin_b, nullptr, out, NA, 0);
}